// round 11
// baseline (speedup 1.0000x reference)
#include <cuda_runtime.h>
#include <cuda_bf16.h>
#include <cuda_fp16.h>
#include <math.h>
#include <cstdint>

#define NN 2048
#define CC 16
#define FF 1024
#define NHEADS 4
#define KF 4096
#define EE 16384
#define NPIX 131072
#define BNEPS 1e-5f
#define KA 1024

// ---------------- scratch (static device memory; no allocation) ----------------
__device__ __half d_Af[NN * KA];
__device__ __half d_Blh[KF * KA];
__device__ __half d_Brh[KF * KA];
__device__ __half d_xl[NN * KF];
__device__ __half d_xr[NN * KF];
__device__ float d_Sx[16];
__device__ float d_Sxx[136];
__device__ float d_A[256];
__device__ float d_dv[16];
__device__ int   d_cnt[NN];
__device__ int   d_rowstart[NN + 1];
__device__ int   d_cursor[NN];
__device__ int   d_esrc[EE + NN];
__device__ float d_b2sum[16], d_b2sq[16];

// ---------------- helpers ----------------
__device__ __forceinline__ uint32_t smem_u32(const void* p) {
    uint32_t a;
    asm("{ .reg .u64 t; cvta.to.shared.u64 t, %1; cvt.u32.u64 %0, t; }" : "=r"(a) : "l"(p));
    return a;
}
__device__ __forceinline__ void cp16(uint32_t dst, const void* src) {
    asm volatile("cp.async.cg.shared.global [%0], [%1], 16;" :: "r"(dst), "l"(src) : "memory");
}
__device__ __forceinline__ void ldm4(uint32_t* r, uint32_t addr) {
    asm volatile("ldmatrix.sync.aligned.m8n8.x4.shared.b16 {%0,%1,%2,%3}, [%4];"
                 : "=r"(r[0]), "=r"(r[1]), "=r"(r[2]), "=r"(r[3]) : "r"(addr));
}
__device__ __forceinline__ void mma16816(float* d, const uint32_t* a, uint32_t b0, uint32_t b1) {
    asm volatile("mma.sync.aligned.m16n8k16.row.col.f32.f16.f16.f32 "
                 "{%0,%1,%2,%3}, {%4,%5,%6,%7}, {%8,%9}, {%0,%1,%2,%3};"
                 : "+f"(d[0]), "+f"(d[1]), "+f"(d[2]), "+f"(d[3])
                 : "r"(a[0]), "r"(a[1]), "r"(a[2]), "r"(a[3]), "r"(b0), "r"(b1));
}

// ---------------- pre1: channel stats (blocks 0-255) || edge histogram (256-319) ----------------
__global__ __launch_bounds__(256) void k_pre1(const float* __restrict__ x,
                                              const int* __restrict__ ei) {
    int b = blockIdx.x;
    int t = threadIdx.x;
    if (b < 256) {
        __shared__ float sm[16][513];
        int base = b * 512;
        for (int i = t; i < 16 * 512; i += 256) {
            int c = i >> 9, s = i & 511;
            int q = base + s;
            sm[c][s] = x[(q >> 6) * 1024 + c * 64 + (q & 63)];
        }
        __syncthreads();
        if (t < 16) {
            float acc = 0.f;
            #pragma unroll 8
            for (int s = 0; s < 512; s++) acc += sm[t][s];
            atomicAdd(&d_Sx[t], acc);
        } else if (t < 152) {
            int p = t - 16;
            int c = 0, r = p;
            while (r >= 16 - c) { r -= 16 - c; c++; }
            int c2 = c + r;
            float acc = 0.f;
            #pragma unroll 8
            for (int s = 0; s < 512; s++) acc += sm[c][s] * sm[c2][s];
            atomicAdd(&d_Sxx[p], acc);
        }
    } else {
        int e = (b - 256) * 256 + t;
        if (e < EE) {
            int s = ei[e], d = ei[EE + e];
            if (s != d) atomicAdd(&d_cnt[d], 1);
        }
    }
}

// ---------------- pre2: block 0 = bnfold; block 1 = shuffle scan (2 barriers) ----------------
__global__ __launch_bounds__(1024) void k_pre2(const float* __restrict__ w1, const float* __restrict__ b1,
                                               const float* __restrict__ g1, const float* __restrict__ be1) {
    int t = threadIdx.x;
    if (blockIdx.x == 0) {
        __shared__ float mx[16], cov[16][16];
        if (t < 16) mx[t] = d_Sx[t] * (1.0f / NPIX);
        __syncthreads();
        if (t < 136) {
            int c = 0, r = t;
            while (r >= 16 - c) { r -= 16 - c; c++; }
            int c2 = c + r;
            float cv = d_Sxx[t] * (1.0f / NPIX) - mx[c] * mx[c2];
            cov[c][c2] = cv; cov[c2][c] = cv;
        }
        __syncthreads();
        if (t < 16) d_Sx[t] = 0.f;
        if (t < 136) d_Sxx[t] = 0.f;
        if (t < 256) {
            int o = t >> 4, c = t & 15;
            float wc = w1[o * 16 + c];
            float pm = wc * mx[c];
            float pv = 0.f;
            #pragma unroll
            for (int c2 = 0; c2 < 16; c2++) pv += w1[o * 16 + c2] * cov[c][c2];
            pv *= wc;
            #pragma unroll
            for (int off = 8; off > 0; off >>= 1) {
                pm += __shfl_down_sync(0xffffffffu, pm, off, 16);
                pv += __shfl_down_sync(0xffffffffu, pv, off, 16);
            }
            float m = __shfl_sync(0xffffffffu, pm, (t & 16), 32) + b1[o];
            float var = __shfl_sync(0xffffffffu, pv, (t & 16), 32);
            float rs = rsqrtf(var + BNEPS) * g1[o];
            d_A[o * 16 + c] = wc * rs;
            if (c == 0) d_dv[o] = (b1[o] - m) * rs + be1[o];
        }
    } else {
        // shuffle-based scan over 2048 counts (+1 self loop), 2 elements/thread
        __shared__ int wsum[32];
        int lane = t & 31, warp = t >> 5;
        int a = d_cnt[2 * t] + 1;
        int bb = d_cnt[2 * t + 1] + 1;
        d_cnt[2 * t] = 0; d_cnt[2 * t + 1] = 0;
        int s = a + bb;
        #pragma unroll
        for (int off = 1; off < 32; off <<= 1) {
            int v = __shfl_up_sync(0xffffffffu, s, off);
            if (lane >= off) s += v;
        }
        if (lane == 31) wsum[warp] = s;
        __syncthreads();
        if (warp == 0) {
            int w = wsum[lane];
            #pragma unroll
            for (int off = 1; off < 32; off <<= 1) {
                int v = __shfl_up_sync(0xffffffffu, w, off);
                if (lane >= off) w += v;
            }
            wsum[lane] = w;
        }
        __syncthreads();
        int base = (warp > 0) ? wsum[warp - 1] : 0;
        int incl = base + s;                 // inclusive through element 2t+1
        int excl = incl - a - bb;            // exclusive before element 2t
        d_rowstart[2 * t] = excl;     d_cursor[2 * t] = excl;
        d_rowstart[2 * t + 1] = excl + a; d_cursor[2 * t + 1] = excl + a;
        if (t == 1023) d_rowstart[2048] = incl;
    }
}

// ---------------- pre3: scatter (b<72) || yf (b<584) || convB wl (b<4680) || convB wr ----------------
__device__ __forceinline__ void convB_body(const float* __restrict__ w,
                                           __half* __restrict__ Bf,
                                           int bx, int by, int t) {
    __shared__ float ts[32][33];
    int nb = bx * 32;
    int kb = by * 32;
    int col = t & 31, trow = t >> 5;
    #pragma unroll
    for (int i = 0; i < 4; i++) {
        int r = trow + i * 8;
        ts[r][col] = w[(size_t)(kb + r) * 4096 + nb + col];
    }
    __syncthreads();
    int nloc = t >> 3, kq = (t & 7) * 4;
    __half hv[4];
    #pragma unroll
    for (int j = 0; j < 4; j++) hv[j] = __float2half(ts[kq + j][nloc]);
    size_t base = (size_t)(nb + nloc) * KA + kb + kq;
    *(uint2*)(Bf + base) = *(uint2*)hv;
}

__global__ __launch_bounds__(256) void k_pre3(const int* __restrict__ ei,
                                              const float* __restrict__ x,
                                              const float* __restrict__ wl,
                                              const float* __restrict__ wr) {
    int b = blockIdx.x;
    int t = threadIdx.x;
    if (b < 72) {
        if (b == 0 && t < 16) { d_b2sum[t] = 0.f; d_b2sq[t] = 0.f; }
        int i = b * 256 + t;
        if (i < NN) {
            int pos = atomicAdd(&d_cursor[i], 1);
            d_esrc[pos] = i;
        } else if (i < NN + EE) {
            int e = i - NN;
            int s = ei[e], d = ei[EE + e];
            if (s != d) { int pos = atomicAdd(&d_cursor[d], 1); d_esrc[pos] = s; }
        }
    } else if (b < 584) {
        __shared__ float As[256], dvs[16];
        if (t < 256) As[t] = d_A[t];
        if (t < 16) dvs[t] = d_dv[t];
        __syncthreads();
        int q = (b - 72) * 256 + t;
        int n = q >> 6, p = q & 63;
        float xv[16];
        #pragma unroll
        for (int c = 0; c < 16; c++) xv[c] = x[n * 1024 + c * 64 + p];
        #pragma unroll
        for (int o = 0; o < 16; o++) {
            float s = dvs[o];
            #pragma unroll
            for (int c = 0; c < 16; c++) s += As[o * 16 + c] * xv[c];
            int f = o * 64 + p;
            d_Af[(size_t)n * KA + f] = __float2half(s);
        }
    } else if (b < 4680) {
        int i = b - 584;
        convB_body(wl, d_Blh, i & 127, i >> 7, t);
    } else {
        int i = b - 4680;
        convB_body(wr, d_Brh, i & 127, i >> 7, t);
    }
}

// ---------------- mma.sync fp16 GEMM, 128x256, 512 thr, 3-stage, B-frag ks-pipeline ----------------
#define STAGE_B 49152
#define GSM_TOTAL (3 * STAGE_B)

#define ISSUE_CHUNK(kb, buf) do {                                               \
    uint32_t sA_ = sbase + (buf) * STAGE_B;                                     \
    uint32_t sB_ = sA_ + 16384;                                                 \
    _Pragma("unroll")                                                           \
    for (int i_ = 0; i_ < 2; i_++) {                                            \
        int id_ = t + i_ * 512, r_ = id_ >> 3, c_ = id_ & 7;                    \
        cp16(sA_ + r_ * 128 + ((c_ ^ (r_ & 7)) << 4),                           \
             Ag + (size_t)r_ * KA + (kb) * 64 + c_ * 8);                        \
    }                                                                           \
    _Pragma("unroll")                                                           \
    for (int i_ = 0; i_ < 4; i_++) {                                            \
        int id_ = t + i_ * 512, r_ = id_ >> 3, c_ = id_ & 7;                    \
        cp16(sB_ + r_ * 128 + ((c_ ^ (r_ & 7)) << 4),                           \
             Bg + (size_t)r_ * KA + (kb) * 64 + c_ * 8);                        \
    }                                                                           \
    asm volatile("cp.async.commit_group;" ::: "memory");                        \
} while (0)

__global__ __launch_bounds__(512) void k_gemm(const float* __restrict__ biasl,
                                              const float* __restrict__ biasr) {
    extern __shared__ char smem[];
    uint32_t sbase = smem_u32(smem);
    int t = threadIdx.x, lane = t & 31, wid = t >> 5;
    int wm = wid & 3, wn = wid >> 2;
    int bm = blockIdx.y * 128;
    int bx = blockIdx.x;
    int isR = bx >= 16;
    int bn = (bx - (isR ? 16 : 0)) * 256;

    const __half* Ag = d_Af + (size_t)bm * KA;
    const __half* Bg = (isR ? d_Brh : d_Blh) + (size_t)bn * KA;
    const float* bias = isR ? biasr : biasl;
    __half* C = isR ? d_xr : d_xl;

    float acc[2][8][4];
    #pragma unroll
    for (int mi = 0; mi < 2; mi++)
        #pragma unroll
        for (int nj = 0; nj < 8; nj++)
            #pragma unroll
            for (int k = 0; k < 4; k++) acc[mi][nj][k] = 0.f;

    ISSUE_CHUNK(0, 0);
    ISSUE_CHUNK(1, 1);

    int g = lane >> 3, li = lane & 7;
    // precomputed intra-tile offsets
    int arow = wm * 32 + (g & 1) * 8 + li;       // + mi*16
    int brow = wn * 64 + (g >> 1) * 8 + li;      // + nt*16
    int aun = (g >> 1);                          // + ks*2
    int bun = (g & 1);                           // + ks*2

    int buf = 0;
    for (int kb = 0; kb < 16; kb++) {
        asm volatile("cp.async.wait_group 1;" ::: "memory");
        __syncthreads();
        if (kb + 2 < 16) {
            int nb_ = (kb + 2) % 3;
            ISSUE_CHUNK(kb + 2, nb_);
        } else {
            asm volatile("cp.async.commit_group;" ::: "memory");
        }
        uint32_t sA = sbase + buf * STAGE_B;
        uint32_t sB = sA + 16384;

        uint32_t bf[2][4][4];
        // prologue: B fragments for ks=0
        #pragma unroll
        for (int nt = 0; nt < 4; nt++) {
            int row = brow + nt * 16;
            ldm4(bf[0][nt], sB + row * 128 + ((bun ^ (row & 7)) << 4));
        }
        #pragma unroll
        for (int ks = 0; ks < 4; ks++) {
            int cur = ks & 1, nxtp = cur ^ 1;
            uint32_t af[2][4];
            // A fragments for current ks
            #pragma unroll
            for (int mi = 0; mi < 2; mi++) {
                int row = arow + mi * 16;
                int unit = ks * 2 + aun;
                ldm4(af[mi], sA + row * 128 + ((unit ^ (row & 7)) << 4));
            }
            // prefetch B fragments for next ks (overlaps with mma below)
            if (ks < 3) {
                #pragma unroll
                for (int nt = 0; nt < 4; nt++) {
                    int row = brow + nt * 16;
                    int unit = (ks + 1) * 2 + bun;
                    ldm4(bf[nxtp][nt], sB + row * 128 + ((unit ^ (row & 7)) << 4));
                }
            }
            #pragma unroll
            for (int mi = 0; mi < 2; mi++)
                #pragma unroll
                for (int nt = 0; nt < 4; nt++) {
                    mma16816(acc[mi][nt * 2 + 0], af[mi], bf[cur][nt][0], bf[cur][nt][1]);
                    mma16816(acc[mi][nt * 2 + 1], af[mi], bf[cur][nt][2], bf[cur][nt][3]);
                }
        }
        buf = (buf + 1) % 3;
    }

    #pragma unroll
    for (int mi = 0; mi < 2; mi++) {
        int gm0 = bm + wm * 32 + mi * 16 + (lane >> 2);
        #pragma unroll
        for (int nj = 0; nj < 8; nj++) {
            int gn = bn + wn * 64 + nj * 8 + (lane & 3) * 2;
            float2 bv = *(const float2*)(bias + gn);
            __half2 h0 = __floats2half2_rn(acc[mi][nj][0] + bv.x, acc[mi][nj][1] + bv.y);
            __half2 h1 = __floats2half2_rn(acc[mi][nj][2] + bv.x, acc[mi][nj][3] + bv.y);
            *(__half2*)(C + (size_t)gm0 * 4096 + gn) = h0;
            *(__half2*)(C + (size_t)(gm0 + 8) * 4096 + gn) = h1;
        }
    }
}

// ---------------- fused GAT (online softmax, prefetched) + conv2 + BN2 stats ----------------
__global__ __launch_bounds__(256) void k_gat(const float* __restrict__ att,
                                             const float* __restrict__ biasg,
                                             const float* __restrict__ w2,
                                             const float* __restrict__ b2,
                                             float* __restrict__ outp) {
    __shared__ float gs[4096];
    __shared__ float w2s[1024];
    __shared__ float red[2][8][4];
    __shared__ float ssum[16], ssq[16];
    int n = blockIdx.x;
    int t = threadIdx.x;
    int lane = t & 31, warp = t >> 5;

    for (int i = t; i < 1024; i += 256) w2s[i] = w2[i];
    if (t < 16) { ssum[t] = 0.f; ssq[t] = 0.f; }

    const __half2* xr2 = (const __half2*)d_xr + (size_t)n * 2048;
    float2 attv[8], xrv[8], acc[8];
    #pragma unroll
    for (int j = 0; j < 8; j++) {
        int f = 2 * t + 512 * j;
        attv[j] = *(const float2*)(att + f);
        xrv[j] = __half22float2(xr2[t + 256 * j]);
        acc[j] = make_float2(0.f, 0.f);
    }
    float mh[4] = {-3.0e38f, -3.0e38f, -3.0e38f, -3.0e38f};
    float lh[4] = {0.f, 0.f, 0.f, 0.f};

    int beg = d_rowstart[n], end = d_rowstart[n + 1];
    uint32_t cur[8], nxt[8];
    {
        int src = d_esrc[beg];
        const uint32_t* p = (const uint32_t*)d_xl + (size_t)src * 2048;
        #pragma unroll
        for (int j = 0; j < 8; j++) cur[j] = p[t + 256 * j];
    }
    for (int e = beg; e < end; e++) {
        if (e + 1 < end) {
            int src2 = d_esrc[e + 1];
            const uint32_t* p = (const uint32_t*)d_xl + (size_t)src2 * 2048;
            #pragma unroll
            for (int j = 0; j < 8; j++) nxt[j] = p[t + 256 * j];
        }
        float2 xf[8];
        #pragma unroll
        for (int j = 0; j < 8; j++) xf[j] = __half22float2(*(__half2*)&cur[j]);

        float part[4] = {0.f, 0.f, 0.f, 0.f};
        #pragma unroll
        for (int j = 0; j < 8; j++) {
            float zx = xf[j].x + xrv[j].x;
            float zy = xf[j].y + xrv[j].y;
            float lx = zx > 0.f ? zx : 0.2f * zx;
            float ly = zy > 0.f ? zy : 0.2f * zy;
            part[j >> 1] += attv[j].x * lx + attv[j].y * ly;
        }
        #pragma unroll
        for (int off = 16; off > 0; off >>= 1) {
            #pragma unroll
            for (int h = 0; h < 4; h++)
                part[h] += __shfl_down_sync(0xffffffffu, part[h], off);
        }
        int pb = e & 1;
        if (lane == 0) {
            #pragma unroll
            for (int h = 0; h < 4; h++) red[pb][warp][h] = part[h];
        }
        __syncthreads();
        float sc[4], cf[4];
        #pragma unroll
        for (int h = 0; h < 4; h++) {
            float L = red[pb][0][h] + red[pb][1][h] + red[pb][2][h] + red[pb][3][h]
                    + red[pb][4][h] + red[pb][5][h] + red[pb][6][h] + red[pb][7][h];
            float nm = fmaxf(mh[h], L);
            sc[h] = __expf(mh[h] - nm);
            cf[h] = __expf(L - nm);
            mh[h] = nm;
            lh[h] = lh[h] * sc[h] + cf[h];
        }
        #pragma unroll
        for (int j = 0; j < 8; j++) {
            int h = j >> 1;
            acc[j].x = acc[j].x * sc[h] + cf[h] * xf[j].x;
            acc[j].y = acc[j].y * sc[h] + cf[h] * xf[j].y;
        }
        #pragma unroll
        for (int j = 0; j < 8; j++) cur[j] = nxt[j];
    }

    #pragma unroll
    for (int j = 0; j < 8; j++) {
        int f = 2 * t + 512 * j;
        int h = j >> 1;
        float2 bgv = *(const float2*)(biasg + f);
        float2 g;
        g.x = acc[j].x / lh[h] + bgv.x;
        g.y = acc[j].y / lh[h] + bgv.y;
        *(float2*)(gs + f) = g;
    }
    __syncthreads();

    #pragma unroll
    for (int i = 0; i < 4; i++) {
        int oidx = t + 256 * i;
        int c = oidx >> 6, p = oidx & 63;
        float s = b2[c];
        #pragma unroll 16
        for (int ch = 0; ch < 64; ch++) s += w2s[c * 64 + ch] * gs[ch * 64 + p];
        outp[n * 1024 + oidx] = s;
        float vs = s, vq = s * s;
        #pragma unroll
        for (int off = 16; off > 0; off >>= 1) {
            vs += __shfl_down_sync(0xffffffffu, vs, off);
            vq += __shfl_down_sync(0xffffffffu, vq, off);
        }
        if (lane == 0) { atomicAdd(&ssum[c], vs); atomicAdd(&ssq[c], vq); }
    }
    __syncthreads();
    if (t < 16) {
        atomicAdd(&d_b2sum[t], ssum[t]);
        atomicAdd(&d_b2sq[t], ssq[t]);
    }
}

// ---------------- BN2 finalize + residual (merged) ----------------
__global__ void k_final(const float* __restrict__ x, float* __restrict__ o,
                        const float* __restrict__ g2, const float* __restrict__ be2) {
    __shared__ float sc[16], sh[16];
    int t = threadIdx.x;
    if (t < 16) {
        float mean = d_b2sum[t] * (1.0f / NPIX);
        float var = d_b2sq[t] * (1.0f / NPIX) - mean * mean;
        float s = g2[t] * rsqrtf(var + BNEPS);
        sc[t] = s;
        sh[t] = be2[t] - mean * s;
    }
    __syncthreads();
    int i = blockIdx.x * 256 + t;
    int c = (i >> 6) & 15;
    o[i] = o[i] * sc[c] + sh[c] + x[i];
}

// ---------------- launch (single stream, 6 kernels) ----------------
extern "C" void kernel_launch(void* const* d_in, const int* in_sizes, int n_in,
                              void* d_out, int out_size) {
    const float* x    = (const float*)d_in[0];
    const int*   ei   = (const int*)  d_in[1];
    const float* w1   = (const float*)d_in[2];
    const float* b1   = (const float*)d_in[3];
    const float* g1   = (const float*)d_in[4];
    const float* be1  = (const float*)d_in[5];
    const float* wl   = (const float*)d_in[6];
    const float* bl   = (const float*)d_in[7];
    const float* wr   = (const float*)d_in[8];
    const float* br   = (const float*)d_in[9];
    const float* att  = (const float*)d_in[10];
    const float* bg   = (const float*)d_in[11];
    const float* w2   = (const float*)d_in[12];
    const float* b2   = (const float*)d_in[13];
    const float* g2   = (const float*)d_in[14];
    const float* be2  = (const float*)d_in[15];
    float* outp = (float*)d_out;

    static int inited = 0;
    if (!inited) {
        cudaFuncSetAttribute(k_gemm, cudaFuncAttributeMaxDynamicSharedMemorySize, GSM_TOTAL);
        inited = 1;
    }

    k_pre1<<<320, 256>>>(x, ei);
    k_pre2<<<2, 1024>>>(w1, b1, g1, be1);
    k_pre3<<<8776, 256>>>(ei, x, wl, wr);
    dim3 gg(32, 16);
    k_gemm<<<gg, 512, GSM_TOTAL>>>(bl, br);
    k_gat<<<NN, 256>>>(att, bg, w2, b2, outp);
    k_final<<<8192, 256>>>(x, outp, g2, be2);
}

// round 12
// speedup vs baseline: 1.0412x; 1.0412x over previous
#include <cuda_runtime.h>
#include <cuda_bf16.h>
#include <cuda_fp16.h>
#include <math.h>
#include <cstdint>

#define NN 2048
#define CC 16
#define FF 1024
#define NHEADS 4
#define KF 4096
#define EE 16384
#define NPIX 131072
#define BNEPS 1e-5f
#define KA 1024

// ---------------- scratch (static device memory; no allocation) ----------------
__device__ __half d_Af[NN * KA];
__device__ __half d_Blh[KF * KA];
__device__ __half d_Brh[KF * KA];
__device__ __half d_xl[NN * KF];
__device__ __half d_xr[NN * KF];
__device__ float d_Sx[16];
__device__ float d_Sxx[136];
__device__ float d_A[256];
__device__ float d_dv[16];
__device__ int   d_cnt[NN];
__device__ int   d_rowstart[NN + 1];
__device__ int   d_cursor[NN];
__device__ int   d_esrc[EE + NN];
__device__ float d_b2sum[16], d_b2sq[16];
__device__ int   d_tick;                          // zero at start; self-reset

// ---------------- helpers ----------------
__device__ __forceinline__ uint32_t smem_u32(const void* p) {
    uint32_t a;
    asm("{ .reg .u64 t; cvta.to.shared.u64 t, %1; cvt.u32.u64 %0, t; }" : "=r"(a) : "l"(p));
    return a;
}
__device__ __forceinline__ void cp16(uint32_t dst, const void* src) {
    asm volatile("cp.async.cg.shared.global [%0], [%1], 16;" :: "r"(dst), "l"(src) : "memory");
}
__device__ __forceinline__ void ldm4(uint32_t* r, uint32_t addr) {
    asm volatile("ldmatrix.sync.aligned.m8n8.x4.shared.b16 {%0,%1,%2,%3}, [%4];"
                 : "=r"(r[0]), "=r"(r[1]), "=r"(r[2]), "=r"(r[3]) : "r"(addr));
}
__device__ __forceinline__ void mma16816(float* d, const uint32_t* a, uint32_t b0, uint32_t b1) {
    asm volatile("mma.sync.aligned.m16n8k16.row.col.f32.f16.f16.f32 "
                 "{%0,%1,%2,%3}, {%4,%5,%6,%7}, {%8,%9}, {%0,%1,%2,%3};"
                 : "+f"(d[0]), "+f"(d[1]), "+f"(d[2]), "+f"(d[3])
                 : "r"(a[0]), "r"(a[1]), "r"(a[2]), "r"(a[3]), "r"(b0), "r"(b1));
}

// ---------------- pre1: stats (b<256) || hist (b<320); LAST block does bnfold + scan ----------------
__global__ __launch_bounds__(256) void k_pre1(const float* __restrict__ x,
                                              const int* __restrict__ ei,
                                              const float* __restrict__ w1, const float* __restrict__ b1,
                                              const float* __restrict__ g1, const float* __restrict__ be1) {
    int b = blockIdx.x;
    int t = threadIdx.x;
    if (b < 256) {
        __shared__ float sm[16][513];
        int base = b * 512;
        for (int i = t; i < 16 * 512; i += 256) {
            int c = i >> 9, s = i & 511;
            int q = base + s;
            sm[c][s] = x[(q >> 6) * 1024 + c * 64 + (q & 63)];
        }
        __syncthreads();
        if (t < 16) {
            float acc = 0.f;
            #pragma unroll 8
            for (int s = 0; s < 512; s++) acc += sm[t][s];
            atomicAdd(&d_Sx[t], acc);
        } else if (t < 152) {
            int p = t - 16;
            int c = 0, r = p;
            while (r >= 16 - c) { r -= 16 - c; c++; }
            int c2 = c + r;
            float acc = 0.f;
            #pragma unroll 8
            for (int s = 0; s < 512; s++) acc += sm[c][s] * sm[c2][s];
            atomicAdd(&d_Sxx[p], acc);
        }
    } else {
        int e = (b - 256) * 256 + t;
        if (e < EE) {
            int s = ei[e], d = ei[EE + e];
            if (s != d) atomicAdd(&d_cnt[d], 1);
        }
    }
    // ---- ticket: last finishing block runs bnfold + scan ----
    __shared__ int isLast;
    __syncthreads();
    if (t == 0) {
        __threadfence();
        int done = atomicAdd(&d_tick, 1);
        isLast = (done == 319);
        if (isLast) d_tick = 0;            // reset for next replay
    }
    __syncthreads();
    if (!isLast) return;
    __threadfence();                        // acquire all blocks' writes

    // ---- bnfold (256 threads) ----
    {
        __shared__ float mx[16], cov[16][16];
        if (t < 16) mx[t] = d_Sx[t] * (1.0f / NPIX);
        __syncthreads();
        if (t < 136) {
            int c = 0, r = t;
            while (r >= 16 - c) { r -= 16 - c; c++; }
            int c2 = c + r;
            float cv = d_Sxx[t] * (1.0f / NPIX) - mx[c] * mx[c2];
            cov[c][c2] = cv; cov[c2][c] = cv;
        }
        __syncthreads();
        if (t < 16) d_Sx[t] = 0.f;
        if (t < 136) d_Sxx[t] = 0.f;
        int o = t >> 4, c = t & 15;
        float wc = w1[o * 16 + c];
        float pm = wc * mx[c];
        float pv = 0.f;
        #pragma unroll
        for (int c2 = 0; c2 < 16; c2++) pv += w1[o * 16 + c2] * cov[c][c2];
        pv *= wc;
        #pragma unroll
        for (int off = 8; off > 0; off >>= 1) {
            pm += __shfl_down_sync(0xffffffffu, pm, off, 16);
            pv += __shfl_down_sync(0xffffffffu, pv, off, 16);
        }
        float m = __shfl_sync(0xffffffffu, pm, (t & 16), 32) + b1[o];
        float var = __shfl_sync(0xffffffffu, pv, (t & 16), 32);
        float rs = rsqrtf(var + BNEPS) * g1[o];
        d_A[o * 16 + c] = wc * rs;
        if (c == 0) d_dv[o] = (b1[o] - m) * rs + be1[o];
    }
    __syncthreads();

    // ---- scan: 2048 counts (+1 self-loop), 8 per thread ----
    {
        __shared__ int wsum[8];
        int lane = t & 31, warp = t >> 5;
        int a[8], s = 0;
        #pragma unroll
        for (int k = 0; k < 8; k++) {
            a[k] = d_cnt[8 * t + k] + 1;
            s += a[k];
            d_cnt[8 * t + k] = 0;
        }
        int incl = s;
        #pragma unroll
        for (int off = 1; off < 32; off <<= 1) {
            int v = __shfl_up_sync(0xffffffffu, incl, off);
            if (lane >= off) incl += v;
        }
        if (lane == 31) wsum[warp] = incl;
        __syncthreads();
        if (t == 0) {
            int run = 0;
            #pragma unroll
            for (int w = 0; w < 8; w++) { run += wsum[w]; wsum[w] = run; }
        }
        __syncthreads();
        int base = (warp > 0) ? wsum[warp - 1] : 0;
        int running = base + incl - s;      // exclusive start for this thread's 8 elems
        #pragma unroll
        for (int k = 0; k < 8; k++) {
            int idx = 8 * t + k;
            d_rowstart[idx] = running;
            d_cursor[idx] = running;
            running += a[k];
        }
        if (t == 255) d_rowstart[2048] = running;
    }
}

// ---------------- pre3: scatter (b<72) || yf (b<584) || convB wl (b<4680) || convB wr ----------------
__device__ __forceinline__ void convB_body(const float* __restrict__ w,
                                           __half* __restrict__ Bf,
                                           int bx, int by, int t) {
    __shared__ float ts[32][33];
    int nb = bx * 32;
    int kb = by * 32;
    int col = t & 31, trow = t >> 5;
    #pragma unroll
    for (int i = 0; i < 4; i++) {
        int r = trow + i * 8;
        ts[r][col] = w[(size_t)(kb + r) * 4096 + nb + col];
    }
    __syncthreads();
    int nloc = t >> 3, kq = (t & 7) * 4;
    __half hv[4];
    #pragma unroll
    for (int j = 0; j < 4; j++) hv[j] = __float2half(ts[kq + j][nloc]);
    size_t base = (size_t)(nb + nloc) * KA + kb + kq;
    *(uint2*)(Bf + base) = *(uint2*)hv;
}

__global__ __launch_bounds__(256) void k_pre3(const int* __restrict__ ei,
                                              const float* __restrict__ x,
                                              const float* __restrict__ wl,
                                              const float* __restrict__ wr) {
    int b = blockIdx.x;
    int t = threadIdx.x;
    if (b < 72) {
        if (b == 0 && t < 16) { d_b2sum[t] = 0.f; d_b2sq[t] = 0.f; }
        int i = b * 256 + t;
        if (i < NN) {
            int pos = atomicAdd(&d_cursor[i], 1);
            d_esrc[pos] = i;
        } else if (i < NN + EE) {
            int e = i - NN;
            int s = ei[e], d = ei[EE + e];
            if (s != d) { int pos = atomicAdd(&d_cursor[d], 1); d_esrc[pos] = s; }
        }
    } else if (b < 584) {
        __shared__ float As[256], dvs[16];
        if (t < 256) As[t] = d_A[t];
        if (t < 16) dvs[t] = d_dv[t];
        __syncthreads();
        int q = (b - 72) * 256 + t;
        int n = q >> 6, p = q & 63;
        float xv[16];
        #pragma unroll
        for (int c = 0; c < 16; c++) xv[c] = x[n * 1024 + c * 64 + p];
        #pragma unroll
        for (int o = 0; o < 16; o++) {
            float s = dvs[o];
            #pragma unroll
            for (int c = 0; c < 16; c++) s += As[o * 16 + c] * xv[c];
            int f = o * 64 + p;
            d_Af[(size_t)n * KA + f] = __float2half(s);
        }
    } else if (b < 4680) {
        int i = b - 584;
        convB_body(wl, d_Blh, i & 127, i >> 7, t);
    } else {
        int i = b - 4680;
        convB_body(wr, d_Brh, i & 127, i >> 7, t);
    }
}

// ---------------- mma.sync fp16 GEMM: 128x256 tile, 512 thr, K-chunk 128, 2-stage ----------------
// stage: A 128 rows x 256B = 32KB @ 0; B 256 rows x 256B = 64KB @ 32768. STAGE 96KB x2.
#define STAGE_B 98304
#define GSM_TOTAL (2 * STAGE_B)

// address within a 256B row: unit u (16B, 0..15) at row r:
//   (u>>3)*128 + (((u&7) ^ (r&7)) << 4)
#define ISSUE_CHUNK(kb, buf) do {                                               \
    uint32_t sA_ = sbase + (buf) * STAGE_B;                                     \
    uint32_t sB_ = sA_ + 32768;                                                 \
    _Pragma("unroll")                                                           \
    for (int i_ = 0; i_ < 4; i_++) {                                            \
        int id_ = t + i_ * 512, r_ = id_ >> 4, c_ = id_ & 15;                   \
        cp16(sA_ + r_ * 256 + ((c_ >> 3) << 7) + ((((c_ & 7) ^ (r_ & 7))) << 4),\
             Ag + (size_t)r_ * KA + (kb) * 128 + c_ * 8);                       \
    }                                                                           \
    _Pragma("unroll")                                                           \
    for (int i_ = 0; i_ < 8; i_++) {                                            \
        int id_ = t + i_ * 512, r_ = id_ >> 4, c_ = id_ & 15;                   \
        cp16(sB_ + r_ * 256 + ((c_ >> 3) << 7) + ((((c_ & 7) ^ (r_ & 7))) << 4),\
             Bg + (size_t)r_ * KA + (kb) * 128 + c_ * 8);                       \
    }                                                                           \
    asm volatile("cp.async.commit_group;" ::: "memory");                        \
} while (0)

__global__ __launch_bounds__(512) void k_gemm(const float* __restrict__ biasl,
                                              const float* __restrict__ biasr) {
    extern __shared__ char smem[];
    uint32_t sbase = smem_u32(smem);
    int t = threadIdx.x, lane = t & 31, wid = t >> 5;
    int wm = wid & 3, wn = wid >> 2;
    int bm = blockIdx.y * 128;
    int bx = blockIdx.x;
    int isR = bx >= 16;
    int bn = (bx - (isR ? 16 : 0)) * 256;

    const __half* Ag = d_Af + (size_t)bm * KA;
    const __half* Bg = (isR ? d_Brh : d_Blh) + (size_t)bn * KA;
    const float* bias = isR ? biasr : biasl;
    __half* C = isR ? d_xr : d_xl;

    float acc[2][8][4];
    #pragma unroll
    for (int mi = 0; mi < 2; mi++)
        #pragma unroll
        for (int nj = 0; nj < 8; nj++)
            #pragma unroll
            for (int k = 0; k < 4; k++) acc[mi][nj][k] = 0.f;

    ISSUE_CHUNK(0, 0);
    ISSUE_CHUNK(1, 1);

    int g = lane >> 3, li = lane & 7;
    int arow = wm * 32 + (g & 1) * 8 + li;       // + mi*16
    int brow = wn * 64 + (g >> 1) * 8 + li;      // + nt*16
    int aun = (g >> 1);                          // + ks*2, 0..15
    int bun = (g & 1);

    for (int kb = 0; kb < 8; kb++) {
        asm volatile("cp.async.wait_group 1;" ::: "memory");
        __syncthreads();
        uint32_t sA = sbase + (kb & 1) * STAGE_B;
        uint32_t sB = sA + 32768;
        #pragma unroll
        for (int ks = 0; ks < 8; ks++) {
            uint32_t af[2][4], bf[4][4];
            #pragma unroll
            for (int mi = 0; mi < 2; mi++) {
                int row = arow + mi * 16;
                int unit = ks * 2 + aun;
                ldm4(af[mi], sA + row * 256 + ((unit >> 3) << 7) + ((((unit & 7) ^ (row & 7))) << 4));
            }
            #pragma unroll
            for (int nt = 0; nt < 4; nt++) {
                int row = brow + nt * 16;
                int unit = ks * 2 + bun;
                ldm4(bf[nt], sB + row * 256 + ((unit >> 3) << 7) + ((((unit & 7) ^ (row & 7))) << 4));
            }
            #pragma unroll
            for (int mi = 0; mi < 2; mi++)
                #pragma unroll
                for (int nt = 0; nt < 4; nt++) {
                    mma16816(acc[mi][nt * 2 + 0], af[mi], bf[nt][0], bf[nt][1]);
                    mma16816(acc[mi][nt * 2 + 1], af[mi], bf[nt][2], bf[nt][3]);
                }
        }
        __syncthreads();
        if (kb + 2 < 8) { ISSUE_CHUNK(kb + 2, kb & 1); }
        else { asm volatile("cp.async.commit_group;" ::: "memory"); }
    }

    #pragma unroll
    for (int mi = 0; mi < 2; mi++) {
        int gm0 = bm + wm * 32 + mi * 16 + (lane >> 2);
        #pragma unroll
        for (int nj = 0; nj < 8; nj++) {
            int gn = bn + wn * 64 + nj * 8 + (lane & 3) * 2;
            float2 bv = *(const float2*)(bias + gn);
            __half2 h0 = __floats2half2_rn(acc[mi][nj][0] + bv.x, acc[mi][nj][1] + bv.y);
            __half2 h1 = __floats2half2_rn(acc[mi][nj][2] + bv.x, acc[mi][nj][3] + bv.y);
            *(__half2*)(C + (size_t)gm0 * 4096 + gn) = h0;
            *(__half2*)(C + (size_t)(gm0 + 8) * 4096 + gn) = h1;
        }
    }
}

// ---------------- fused GAT (online softmax, prefetched) + conv2 + BN2 stats ----------------
__global__ __launch_bounds__(256) void k_gat(const float* __restrict__ att,
                                             const float* __restrict__ biasg,
                                             const float* __restrict__ w2,
                                             const float* __restrict__ b2,
                                             float* __restrict__ outp) {
    __shared__ float gs[4096];
    __shared__ float w2s[1024];
    __shared__ float red[2][8][4];
    __shared__ float ssum[16], ssq[16];
    int n = blockIdx.x;
    int t = threadIdx.x;
    int lane = t & 31, warp = t >> 5;

    for (int i = t; i < 1024; i += 256) w2s[i] = w2[i];
    if (t < 16) { ssum[t] = 0.f; ssq[t] = 0.f; }

    const __half2* xr2 = (const __half2*)d_xr + (size_t)n * 2048;
    float2 attv[8], xrv[8], acc[8];
    #pragma unroll
    for (int j = 0; j < 8; j++) {
        int f = 2 * t + 512 * j;
        attv[j] = *(const float2*)(att + f);
        xrv[j] = __half22float2(xr2[t + 256 * j]);
        acc[j] = make_float2(0.f, 0.f);
    }
    float mh[4] = {-3.0e38f, -3.0e38f, -3.0e38f, -3.0e38f};
    float lh[4] = {0.f, 0.f, 0.f, 0.f};

    int beg = d_rowstart[n], end = d_rowstart[n + 1];
    uint32_t cur[8], nxt[8];
    {
        int src = d_esrc[beg];
        const uint32_t* p = (const uint32_t*)d_xl + (size_t)src * 2048;
        #pragma unroll
        for (int j = 0; j < 8; j++) cur[j] = p[t + 256 * j];
    }
    for (int e = beg; e < end; e++) {
        if (e + 1 < end) {
            int src2 = d_esrc[e + 1];
            const uint32_t* p = (const uint32_t*)d_xl + (size_t)src2 * 2048;
            #pragma unroll
            for (int j = 0; j < 8; j++) nxt[j] = p[t + 256 * j];
        }
        float2 xf[8];
        #pragma unroll
        for (int j = 0; j < 8; j++) xf[j] = __half22float2(*(__half2*)&cur[j]);

        float part[4] = {0.f, 0.f, 0.f, 0.f};
        #pragma unroll
        for (int j = 0; j < 8; j++) {
            float zx = xf[j].x + xrv[j].x;
            float zy = xf[j].y + xrv[j].y;
            float lx = zx > 0.f ? zx : 0.2f * zx;
            float ly = zy > 0.f ? zy : 0.2f * zy;
            part[j >> 1] += attv[j].x * lx + attv[j].y * ly;
        }
        #pragma unroll
        for (int off = 16; off > 0; off >>= 1) {
            #pragma unroll
            for (int h = 0; h < 4; h++)
                part[h] += __shfl_down_sync(0xffffffffu, part[h], off);
        }
        int pb = e & 1;
        if (lane == 0) {
            #pragma unroll
            for (int h = 0; h < 4; h++) red[pb][warp][h] = part[h];
        }
        __syncthreads();
        float sc[4], cf[4];
        #pragma unroll
        for (int h = 0; h < 4; h++) {
            float L = red[pb][0][h] + red[pb][1][h] + red[pb][2][h] + red[pb][3][h]
                    + red[pb][4][h] + red[pb][5][h] + red[pb][6][h] + red[pb][7][h];
            float nm = fmaxf(mh[h], L);
            sc[h] = __expf(mh[h] - nm);
            cf[h] = __expf(L - nm);
            mh[h] = nm;
            lh[h] = lh[h] * sc[h] + cf[h];
        }
        #pragma unroll
        for (int j = 0; j < 8; j++) {
            int h = j >> 1;
            acc[j].x = acc[j].x * sc[h] + cf[h] * xf[j].x;
            acc[j].y = acc[j].y * sc[h] + cf[h] * xf[j].y;
        }
        #pragma unroll
        for (int j = 0; j < 8; j++) cur[j] = nxt[j];
    }

    float rinv[4];
    #pragma unroll
    for (int h = 0; h < 4; h++) rinv[h] = 1.0f / lh[h];
    #pragma unroll
    for (int j = 0; j < 8; j++) {
        int f = 2 * t + 512 * j;
        int h = j >> 1;
        float2 bgv = *(const float2*)(biasg + f);
        float2 g;
        g.x = acc[j].x * rinv[h] + bgv.x;
        g.y = acc[j].y * rinv[h] + bgv.y;
        *(float2*)(gs + f) = g;
    }
    __syncthreads();

    #pragma unroll
    for (int i = 0; i < 4; i++) {
        int oidx = t + 256 * i;
        int c = oidx >> 6, p = oidx & 63;
        float s = b2[c];
        #pragma unroll 16
        for (int ch = 0; ch < 64; ch++) s += w2s[c * 64 + ch] * gs[ch * 64 + p];
        outp[n * 1024 + oidx] = s;
        float vs = s, vq = s * s;
        #pragma unroll
        for (int off = 16; off > 0; off >>= 1) {
            vs += __shfl_down_sync(0xffffffffu, vs, off);
            vq += __shfl_down_sync(0xffffffffu, vq, off);
        }
        if (lane == 0) { atomicAdd(&ssum[c], vs); atomicAdd(&ssq[c], vq); }
    }
    __syncthreads();
    if (t < 16) {
        atomicAdd(&d_b2sum[t], ssum[t]);
        atomicAdd(&d_b2sq[t], ssq[t]);
    }
}

// ---------------- BN2 finalize + residual (merged) ----------------
__global__ void k_final(const float* __restrict__ x, float* __restrict__ o,
                        const float* __restrict__ g2, const float* __restrict__ be2) {
    __shared__ float sc[16], sh[16];
    int t = threadIdx.x;
    if (t < 16) {
        float mean = d_b2sum[t] * (1.0f / NPIX);
        float var = d_b2sq[t] * (1.0f / NPIX) - mean * mean;
        float s = g2[t] * rsqrtf(var + BNEPS);
        sc[t] = s;
        sh[t] = be2[t] - mean * s;
    }
    __syncthreads();
    int i = blockIdx.x * 256 + t;
    int c = (i >> 6) & 15;
    o[i] = o[i] * sc[c] + sh[c] + x[i];
}

// ---------------- launch (single stream, 5 kernels) ----------------
extern "C" void kernel_launch(void* const* d_in, const int* in_sizes, int n_in,
                              void* d_out, int out_size) {
    const float* x    = (const float*)d_in[0];
    const int*   ei   = (const int*)  d_in[1];
    const float* w1   = (const float*)d_in[2];
    const float* b1   = (const float*)d_in[3];
    const float* g1   = (const float*)d_in[4];
    const float* be1  = (const float*)d_in[5];
    const float* wl   = (const float*)d_in[6];
    const float* bl   = (const float*)d_in[7];
    const float* wr   = (const float*)d_in[8];
    const float* br   = (const float*)d_in[9];
    const float* att  = (const float*)d_in[10];
    const float* bg   = (const float*)d_in[11];
    const float* w2   = (const float*)d_in[12];
    const float* b2   = (const float*)d_in[13];
    const float* g2   = (const float*)d_in[14];
    const float* be2  = (const float*)d_in[15];
    float* outp = (float*)d_out;

    static int inited = 0;
    if (!inited) {
        cudaFuncSetAttribute(k_gemm, cudaFuncAttributeMaxDynamicSharedMemorySize, GSM_TOTAL);
        inited = 1;
    }

    k_pre1<<<320, 256>>>(x, ei, w1, b1, g1, be1);
    k_pre3<<<8776, 256>>>(ei, x, wl, wr);
    dim3 gg(32, 16);
    k_gemm<<<gg, 512, GSM_TOTAL>>>(bl, br);
    k_gat<<<NN, 256>>>(att, bg, w2, b2, outp);
    k_final<<<8192, 256>>>(x, outp, g2, be2);
}